// round 16
// baseline (speedup 1.0000x reference)
#include <cuda_runtime.h>
#include <cuda_fp16.h>
#include <math.h>
#include <stdint.h>

#define BATCH   256
#define SEQ     256
#define INPUT   128
#define HIDDEN  1024
#define ZS      1026
#define NG      4096          // 4*HIDDEN interleaved: col n' = 4*j + gate
#define KIN     1154
#define KW      1152          // GEMM K = [u(128) | h(1024)]  (x handled rank-2)
#define BK      128
#define NIT     9             // K tiles of 128
#define MHU     1.5f

// smem stage: A [0,16384) | W [16384,49152). 256B rows, swizzle c ^= (row&7).
#define OFF_W   16384
#define STG_B   49152

// Pre-swizzled contiguous K-tile blobs.
__device__ __align__(16) uint4  g_Wblob[32 * 9 * 2048];     // [nblk][kt] 32KB each
__device__ __align__(16) uint4  g_Ablob[2 * 4 * 9 * 1024];  // [p][grp][kt] 16KB each
__device__ __align__(16) float  g_Wx [NG * 2];
__device__ __align__(16) float  g_bint[NG];
__device__ __align__(16) float  g_c[BATCH * HIDDEN];
__device__ __align__(16) float  g_x[2 * BATCH * 2];
__device__ __align__(16) float4 g_part[2 * 4 * 64 * 32];    // [p][grp][row][nblk]

__device__ __forceinline__ float sigf(float x) {
    return __fdividef(1.f, 1.f + __expf(-x));
}
__device__ __forceinline__ float tanhfast(float x) {
    return 2.f * sigf(2.f * x) - 1.f;
}
__device__ __forceinline__ void mma16816(float* c, const uint32_t* a, const uint32_t* b) {
    asm volatile(
        "mma.sync.aligned.m16n8k16.row.col.f32.f16.f16.f32 "
        "{%0,%1,%2,%3}, {%4,%5,%6,%7}, {%8,%9}, {%0,%1,%2,%3};"
        : "+f"(c[0]), "+f"(c[1]), "+f"(c[2]), "+f"(c[3])
        : "r"(a[0]), "r"(a[1]), "r"(a[2]), "r"(a[3]), "r"(b[0]), "r"(b[1]));
}
__device__ __forceinline__ void ldsm4(uint32_t* r, uint32_t addr) {
    asm volatile(
        "ldmatrix.sync.aligned.m8n8.x4.shared.b16 {%0,%1,%2,%3}, [%4];"
        : "=r"(r[0]), "=r"(r[1]), "=r"(r[2]), "=r"(r[3]) : "r"(addr));
}
__device__ __forceinline__ void mwait(uint32_t mbar, uint32_t parity) {
    asm volatile(
        "{\n\t.reg .pred P1;\n\t"
        "WL%=:\n\t"
        "mbarrier.try_wait.parity.acquire.cta.shared::cta.b64 P1, [%0], %1, 0x989680;\n\t"
        "@P1 bra.uni WD%=;\n\t"
        "bra.uni WL%=;\n\t"
        "WD%=:\n\t}" :: "r"(mbar), "r"(parity) : "memory");
}
// byte offset of half k within a (row, kt) of a blob tile (swizzled)
__device__ __forceinline__ uint32_t swz_off(int row, int kc) {
    int chunk = kc >> 3;
    int within = (kc & 7) * 2;
    return (uint32_t)(row * 256 + ((chunk ^ (row & 7)) << 4) + within);
}

// ---------------------------------------------------------------------------
__global__ void repack(const float* __restrict__ WU_w, const float* __restrict__ WU_b) {
    int idx = blockIdx.x * blockDim.x + threadIdx.x;
    const int total = 32 * 9 * 128 * 64;   // (nblk,kt,row,pair)
    for (int i = idx; i < total; i += gridDim.x * blockDim.x) {
        int pc  = i & 63;
        int row = (i >> 6) & 127;
        int t2  = i >> 13;
        int kt  = t2 % 9;
        int nblk = t2 / 9;
        int np = nblk * 128 + row;
        size_t n = (size_t)((np & 3) * HIDDEN + (np >> 2));
        int k2 = kt * 128 + pc * 2;
        __half lo = __float2half(WU_w[n * KIN + k2 + 2]);
        __half hi = __float2half(WU_w[n * KIN + k2 + 3]);
        uint32_t v = (uint32_t)__half_as_ushort(lo) | ((uint32_t)__half_as_ushort(hi) << 16);
        char* base = (char*)g_Wblob + ((size_t)(nblk * 9 + kt) << 15);
        *(uint32_t*)(base + swz_off(row, pc * 2)) = v;
    }
    if (idx < NG) {
        int n = (idx & 3) * HIDDEN + (idx >> 2);
        g_bint[idx] = WU_b[n];
        g_Wx[idx * 2 + 0] = WU_w[(size_t)n * KIN + 0];
        g_Wx[idx * 2 + 1] = WU_w[(size_t)n * KIN + 1];
    }
}

__global__ void init_state(const float* __restrict__ z0,
                           const float* __restrict__ c_z0,
                           const float* __restrict__ rnn_input) {
    int b = blockIdx.x, tid = threadIdx.x;
    int grp = b >> 6, row = b & 63;
    for (int pc = tid; pc < 576; pc += 256) {
        int k2 = pc * 2;
        float v0 = (k2 < 128)     ? rnn_input[(size_t)b * SEQ * INPUT + k2]
                                  : z0[b * ZS + 2 + (k2 - 128)];
        float v1 = (k2 + 1 < 128) ? rnn_input[(size_t)b * SEQ * INPUT + k2 + 1]
                                  : z0[b * ZS + 2 + (k2 + 1 - 128)];
        __half lo = __float2half(v0), hi = __float2half(v1);
        uint32_t v = (uint32_t)__half_as_ushort(lo) | ((uint32_t)__half_as_ushort(hi) << 16);
        int kt = k2 >> 7, kc = k2 & 127;
        char* base = (char*)g_Ablob + ((size_t)((0 * 4 + grp) * 9 + kt) << 14);
        *(uint32_t*)(base + swz_off(row, kc)) = v;
    }
    if (tid < 2) {
        float xv = z0[b * ZS + tid];
        g_x[b * 2 + tid] = xv;
        g_x[BATCH * 2 + b * 2 + tid] = xv;
    }
    for (int j = tid; j < HIDDEN; j += 256)
        g_c[b * HIDDEN + j] = c_z0[b * ZS + 2 + j];
}

// ---------------------------------------------------------------------------
// Per-step kernel: 128 CTAs = 4 grp(64 rows) x 32 nblk(128 gate cols),
// 512 threads / 16 warps, warp grid 4(m) x 4(n), warp tile 16x32.
// BK=128 (9 iters), 3-stage ring via cp.async.bulk + mbarrier.
// Phase A (x_t) hoisted before mainloop to overlap TMA prologue.
// ---------------------------------------------------------------------------
__global__ void __launch_bounds__(512) step_kernel(
    const float* __restrict__ rnn_input, const float* __restrict__ tau,
    const float* __restrict__ alpha_w,   const float* __restrict__ alpha_b,
    const float* __restrict__ Whx_w,     const float* __restrict__ Whx_b,
    float* __restrict__ out, int t)
{
    extern __shared__ __align__(16) unsigned char dynsm[];   // 3*STG_B
    __shared__ __align__(8) unsigned long long mbar[3];
    __shared__ __align__(16) float4 partsm[64][4];
    __shared__ float2 s_wx[128];
    __shared__ float2 s_x[64];

    const int tid  = threadIdx.x;
    const int grp  = blockIdx.x >> 5;
    const int nblk = blockIdx.x & 31;
    const int m0   = grp * 64;
    const int n0   = nblk * 128;
    const int lane = tid & 31, wid = tid >> 5;
    const int warp_m = wid >> 2, warp_n = wid & 3;   // 4x4 warp grid
    const int r = lane >> 2, q = lane & 3;
    const int p  = t & 1;
    const int pn = p ^ 1;

    const uint32_t smb = (uint32_t)__cvta_generic_to_shared(dynsm);
    uint32_t mb[3];
    #pragma unroll
    for (int i = 0; i < 3; i++) mb[i] = (uint32_t)__cvta_generic_to_shared(&mbar[i]);

    if (tid == 0) {
        #pragma unroll
        for (int i = 0; i < 3; i++)
            asm volatile("mbarrier.init.shared.b64 [%0], 1;" :: "r"(mb[i]) : "memory");
    }
    if (tid < 128)
        s_wx[tid] = make_float2(g_Wx[(n0 + tid) * 2], g_Wx[(n0 + tid) * 2 + 1]);
    __syncthreads();

    const char* srcA = (const char*)g_Ablob + ((size_t)(p * 4 + grp) * 9 << 14);
    const char* srcW = (const char*)g_Wblob + ((size_t)nblk * 9 << 15);

    #define ISSUE(kt_) do {                                                      \
        const int _kt = (kt_);                                                   \
        const int _s = _kt % 3;                                                  \
        const uint32_t _d = smb + (uint32_t)_s * STG_B;                          \
        asm volatile("mbarrier.arrive.expect_tx.shared.b64 _, [%0], %1;"         \
                     :: "r"(mb[_s]), "r"(49152u) : "memory");                    \
        asm volatile("cp.async.bulk.shared::cluster.global.mbarrier::complete_tx::bytes " \
                     "[%0], [%1], %2, [%3];"                                     \
                     :: "r"(_d), "l"(srcA + ((size_t)_kt << 14)), "r"(16384u),   \
                        "r"(mb[_s]) : "memory");                                 \
        asm volatile("cp.async.bulk.shared::cluster.global.mbarrier::complete_tx::bytes " \
                     "[%0], [%1], %2, [%3];"                                     \
                     :: "r"(_d + OFF_W), "l"(srcW + ((size_t)_kt << 15)),        \
                        "r"(32768u), "r"(mb[_s]) : "memory");                    \
    } while (0)

    if (tid == 0) { ISSUE(0); ISSUE(1); ISSUE(2); }

    // ---------------- phase A (hoisted): x_t from prev-step parts ----------
    // Overlaps with TMA prologue latency. 16 warps x 4 rows.
    {
        const float4* pp = g_part + (size_t)(pn * 4 + grp) * 64 * 32;
        #pragma unroll 1
        for (int rr = 0; rr < 4; rr++) {
            const int row = wid * 4 + rr;
            const int b = m0 + row;
            float x0, x1;
            if (t == 0) {
                if (lane == 0) {
                    x0 = g_x[BATCH * 2 + b * 2];
                    x1 = g_x[BATCH * 2 + b * 2 + 1];
                }
            } else {
                float4 v = __ldcg(pp + row * 32 + lane);
                #pragma unroll
                for (int off = 16; off > 0; off >>= 1) {
                    v.x += __shfl_xor_sync(0xffffffffu, v.x, off);
                    v.y += __shfl_xor_sync(0xffffffffu, v.y, off);
                    v.z += __shfl_xor_sync(0xffffffffu, v.z, off);
                    v.w += __shfl_xor_sync(0xffffffffu, v.w, off);
                }
                if (lane == 0) {
                    float al0 = sigf(v.x + alpha_b[0]);
                    float al1 = sigf(v.y + alpha_b[1]);
                    float hx0 = v.z + Whx_b[0];
                    float hx1 = v.w + Whx_b[1];
                    float xp0 = g_x[pn * BATCH * 2 + b * 2];
                    float xp1 = g_x[pn * BATCH * 2 + b * 2 + 1];
                    float tv = tau[(size_t)b * SEQ + (t - 1)];
                    float xm0 = (1.f + tv * MHU) * xp0 - (tv * MHU) * xp1;
                    float xm1 = tv * (1.f / MHU) * xp0 + xp1;
                    x0 = al0 * xm0 + (1.f - al0) * hx0;
                    x1 = al1 * xm1 + (1.f - al1) * hx1;
                }
            }
            if (lane == 0) {
                s_x[row] = make_float2(x0, x1);
                if (nblk == 0) {
                    g_x[p * BATCH * 2 + b * 2]     = x0;
                    g_x[p * BATCH * 2 + b * 2 + 1] = x1;
                    if (t > 0) {
                        float* prow = out + ((size_t)b * SEQ + (t - 1)) * ZS;
                        prow[0] = x0;
                        prow[1] = x1;
                    }
                }
            }
        }
    }

    // ---- per-lane ldmatrix swizzled offsets ----
    const int aRow = warp_m * 16 + (lane & 7) + ((lane >> 3) & 1) * 8;
    const int bRow = warp_n * 32 + (lane & 7) + ((lane >> 4) & 1) * 8;
    const int aXor = (aRow >> 1) & 3;
    const int wXor = (bRow >> 1) & 3;
    const uint32_t aBase0 = (uint32_t)(aRow * 256 + ((((lane >> 4) & 1) ^ (aRow & 1)) << 4));
    const uint32_t bBase0 = (uint32_t)(OFF_W + bRow * 256 + ((((lane >> 3) & 1) ^ (bRow & 1)) << 4));
    // +16 rows keeps the same xor phase: bBase1 = bBase0 + 16*256

    float acc[4][4] = {};

    #pragma unroll 1
    for (int it = 0; it < NIT; it++) {
        const int s = it % 3;
        mwait(mb[s], (uint32_t)((it / 3) & 1));

        const uint32_t S = smb + (uint32_t)s * STG_B;
        const uint32_t aB = S + aBase0;
        const uint32_t bB = S + bBase0;

        #pragma unroll
        for (int c = 0; c < 8; c++) {
            uint32_t ah[4], bw0[4], bw1[4];
            ldsm4(ah, aB + (uint32_t)((c ^ aXor) << 5));
            ldsm4(bw0, bB + (uint32_t)((c ^ wXor) << 5));
            ldsm4(bw1, bB + 4096u + (uint32_t)((c ^ wXor) << 5));
            mma16816(acc[0], ah, bw0 + 0);
            mma16816(acc[1], ah, bw0 + 2);
            mma16816(acc[2], ah, bw1 + 0);
            mma16816(acc[3], ah, bw1 + 2);
        }
        __syncthreads();
        if (it + 3 < NIT && tid == 0) ISSUE(it + 3);
    }

    // ---------------- phase B: LSTM gates + dots ----------------
    char* dstA = (char*)g_Ablob + ((size_t)(pn * 4 + grp) * 9 << 14);
    const int parity = q & 1;
    const int jj = q >> 1;
    {
        float d0 = 0.f, d1 = 0.f, d2 = 0.f, d3 = 0.f;
        const int row_blk = warp_m * 16 + r + parity * 8;
        const int b = m0 + row_blk;
        const float2 xv = s_x[row_blk];
        #pragma unroll
        for (int j = 0; j < 4; j++) {
            float c0 = acc[j][0], c1 = acc[j][1], c2 = acc[j][2], c3 = acc[j][3];
            float p0 = __shfl_xor_sync(0xffffffffu, c0, 1);
            float p1 = __shfl_xor_sync(0xffffffffu, c1, 1);
            float p2 = __shfl_xor_sync(0xffffffffu, c2, 1);
            float p3 = __shfl_xor_sync(0xffffffffu, c3, 1);
            float gi, gf, gg, go;
            if (!parity) { gi = c0; gf = c1; gg = p0; go = p1; }
            else         { gi = p2; gf = p3; gg = c2; go = c3; }
            const int jgl = warp_n * 8 + j * 2 + jj;       // local hidden idx 0..31
            const int jg  = nblk * 32 + jgl;               // global hidden idx
            const int npl = 4 * jgl;
            float4 bv = *(const float4*)(g_bint + 4 * jg);
            gi += bv.x + xv.x * s_wx[npl + 0].x + xv.y * s_wx[npl + 0].y;
            gf += bv.y + xv.x * s_wx[npl + 1].x + xv.y * s_wx[npl + 1].y;
            gg += bv.z + xv.x * s_wx[npl + 2].x + xv.y * s_wx[npl + 2].y;
            go += bv.w + xv.x * s_wx[npl + 3].x + xv.y * s_wx[npl + 3].y;
            float co = g_c[b * HIDDEN + jg];
            float cn = sigf(gf) * co + sigf(gi) * tanhfast(gg);
            float h  = sigf(go) * tanhfast(cn);
            g_c[b * HIDDEN + jg] = cn;
            out[((size_t)b * SEQ + t) * ZS + 2 + jg] = h;
            {
                int k = 128 + jg;
                int kt = k >> 7, kc = k & 127;
                *(__half*)(dstA + ((size_t)kt << 14) + swz_off(row_blk, kc)) = __float2half(h);
            }
            d0 += h * alpha_w[jg];
            d1 += h * alpha_w[HIDDEN + jg];
            d2 += h * Whx_w[jg];
            d3 += h * Whx_w[HIDDEN + jg];
        }
        d0 += __shfl_xor_sync(0xffffffffu, d0, 2);
        d1 += __shfl_xor_sync(0xffffffffu, d1, 2);
        d2 += __shfl_xor_sync(0xffffffffu, d2, 2);
        d3 += __shfl_xor_sync(0xffffffffu, d3, 2);
        if (q < 2) partsm[row_blk][warp_n] = make_float4(d0, d1, d2, d3);
    }
    __syncthreads();
    if (tid < 64) {
        float4 s = partsm[tid][0];
        #pragma unroll
        for (int w = 1; w < 4; w++) {
            float4 v = partsm[tid][w];
            s.x += v.x; s.y += v.y; s.z += v.z; s.w += v.w;
        }
        g_part[((size_t)(p * 4 + grp) * 64 + tid) * 32 + nblk] = s;
    }

    // stage u_{t+1}: this CTA covers 2 of the 64 rows (threads 0-255)
    if (t + 1 < SEQ && tid < 256) {
        int row = 2 * nblk + (tid >> 7);
        int col = tid & 127;
        int b = m0 + row;
        float u = rnn_input[((size_t)b * SEQ + (t + 1)) * INPUT + col];
        *(__half*)(dstA + swz_off(row, col)) = __float2half(u);   // kt = 0
    }
}

// ---------------------------------------------------------------------------
__global__ void finalize(const float* __restrict__ tau,
                         const float* __restrict__ alpha_b, const float* __restrict__ Whx_b,
                         const float* __restrict__ c_z0, float* __restrict__ out) {
    int b = blockIdx.x, tid = threadIdx.x;
    __shared__ float2 s_xf;
    if (tid < 32) {
        const float4* pp = g_part + (size_t)(1 * 4 + (b >> 6)) * 64 * 32 + (size_t)(b & 63) * 32;
        float4 v = __ldcg(pp + tid);
        #pragma unroll
        for (int off = 16; off > 0; off >>= 1) {
            v.x += __shfl_xor_sync(0xffffffffu, v.x, off);
            v.y += __shfl_xor_sync(0xffffffffu, v.y, off);
            v.z += __shfl_xor_sync(0xffffffffu, v.z, off);
            v.w += __shfl_xor_sync(0xffffffffu, v.w, off);
        }
        if (tid == 0) {
            float al0 = sigf(v.x + alpha_b[0]);
            float al1 = sigf(v.y + alpha_b[1]);
            float hx0 = v.z + Whx_b[0];
            float hx1 = v.w + Whx_b[1];
            float xp0 = g_x[BATCH * 2 + b * 2];       // parity 1 = step 255
            float xp1 = g_x[BATCH * 2 + b * 2 + 1];
            float tv = tau[(size_t)b * SEQ + (SEQ - 1)];
            float xm0 = (1.f + tv * MHU) * xp0 - (tv * MHU) * xp1;
            float xm1 = tv * (1.f / MHU) * xp0 + xp1;
            float x0 = al0 * xm0 + (1.f - al0) * hx0;
            float x1 = al1 * xm1 + (1.f - al1) * hx1;
            float* prow = out + ((size_t)b * SEQ + (SEQ - 1)) * ZS;
            prow[0] = x0; prow[1] = x1;
            s_xf = make_float2(x0, x1);
        }
    }
    __syncthreads();
    size_t base = (size_t)BATCH * SEQ * ZS;
    float* zf  = out + base + (size_t)b * ZS;
    float* czf = out + base + (size_t)BATCH * ZS + (size_t)b * ZS;
    const float* last = out + ((size_t)b * SEQ + (SEQ - 1)) * ZS;
    for (int k = tid; k < ZS; k += 256) {
        zf[k]  = (k == 0) ? s_xf.x : (k == 1) ? s_xf.y : last[k];
        czf[k] = (k < 2) ? c_z0[b * ZS + k] : g_c[(size_t)b * HIDDEN + (k - 2)];
    }
}

// ---------------------------------------------------------------------------
extern "C" void kernel_launch(void* const* d_in, const int* in_sizes, int n_in,
                              void* d_out, int out_size) {
    const float* rnn_input = (const float*)d_in[0];
    const float* tau       = (const float*)d_in[1];
    const float* z0        = (const float*)d_in[2];
    const float* c_z0      = (const float*)d_in[3];
    const float* WU_w      = (const float*)d_in[4];
    const float* WU_b      = (const float*)d_in[5];
    const float* alpha_w   = (const float*)d_in[6];
    const float* alpha_b   = (const float*)d_in[7];
    const float* Whx_w     = (const float*)d_in[8];
    const float* Whx_b     = (const float*)d_in[9];
    float* out = (float*)d_out;

    static bool attr_set = false;
    if (!attr_set) {
        cudaFuncSetAttribute(step_kernel, cudaFuncAttributeMaxDynamicSharedMemorySize,
                             3 * STG_B);
        attr_set = true;
    }

    repack<<<4096, 256>>>(WU_w, WU_b);
    init_state<<<BATCH, 256>>>(z0, c_z0, rnn_input);
    for (int t = 0; t < SEQ; t++) {
        step_kernel<<<128, 512, 3 * STG_B>>>(rnn_input, tau, alpha_w, alpha_b,
                                             Whx_w, Whx_b, out, t);
    }
    finalize<<<BATCH, 256>>>(tau, alpha_b, Whx_b, c_z0, out);
}

// round 17
// speedup vs baseline: 1.0652x; 1.0652x over previous
#include <cuda_runtime.h>
#include <cuda_fp16.h>
#include <math.h>
#include <stdint.h>

#define BATCH   256
#define SEQ     256
#define INPUT   128
#define HIDDEN  1024
#define ZS      1026
#define NG      4096          // 4*HIDDEN interleaved: col n' = 4*j + gate
#define KIN     1154
#define KW      1152          // GEMM K = [u(128) | h(1024)]  (x handled rank-2)
#define BK      128
#define NIT     9             // K tiles of 128
#define MHU     1.5f

// smem stage: A [0,16384) | W [16384,49152). 256B rows, swizzle c ^= (row&7).
#define OFF_W   16384
#define STG_B   49152
#define SGS     132           // gate buffer row stride (floats)

// Pre-swizzled contiguous K-tile blobs.
__device__ __align__(16) uint4  g_Wblob[32 * 9 * 2048];     // [nblk][kt] 32KB each
__device__ __align__(16) uint4  g_Ablob[2 * 4 * 9 * 1024];  // [p][grp][kt] 16KB each
__device__ __align__(16) float  g_Wx [NG * 2];
__device__ __align__(16) float  g_bint[NG];
__device__ __align__(16) float  g_c[BATCH * HIDDEN];
__device__ __align__(16) float  g_x[2 * BATCH * 2];
__device__ __align__(16) float4 g_part[2 * 4 * 64 * 32];    // [p][grp][row][nblk]

__device__ __forceinline__ float sigf(float x) {
    return __fdividef(1.f, 1.f + __expf(-x));
}
__device__ __forceinline__ float tanhfast(float x) {
    return 2.f * sigf(2.f * x) - 1.f;
}
__device__ __forceinline__ void mma16816(float* c, const uint32_t* a, const uint32_t* b) {
    asm volatile(
        "mma.sync.aligned.m16n8k16.row.col.f32.f16.f16.f32 "
        "{%0,%1,%2,%3}, {%4,%5,%6,%7}, {%8,%9}, {%0,%1,%2,%3};"
        : "+f"(c[0]), "+f"(c[1]), "+f"(c[2]), "+f"(c[3])
        : "r"(a[0]), "r"(a[1]), "r"(a[2]), "r"(a[3]), "r"(b[0]), "r"(b[1]));
}
__device__ __forceinline__ void ldsm4(uint32_t* r, uint32_t addr) {
    asm volatile(
        "ldmatrix.sync.aligned.m8n8.x4.shared.b16 {%0,%1,%2,%3}, [%4];"
        : "=r"(r[0]), "=r"(r[1]), "=r"(r[2]), "=r"(r[3]) : "r"(addr));
}
__device__ __forceinline__ void mwait(uint32_t mbar, uint32_t parity) {
    asm volatile(
        "{\n\t.reg .pred P1;\n\t"
        "WL%=:\n\t"
        "mbarrier.try_wait.parity.acquire.cta.shared::cta.b64 P1, [%0], %1, 0x989680;\n\t"
        "@P1 bra.uni WD%=;\n\t"
        "bra.uni WL%=;\n\t"
        "WD%=:\n\t}" :: "r"(mbar), "r"(parity) : "memory");
}
// byte offset of half k within a (row, kt) of a blob tile (swizzled)
__device__ __forceinline__ uint32_t swz_off(int row, int kc) {
    int chunk = kc >> 3;
    int within = (kc & 7) * 2;
    return (uint32_t)(row * 256 + ((chunk ^ (row & 7)) << 4) + within);
}

// ---------------------------------------------------------------------------
__global__ void repack(const float* __restrict__ WU_w, const float* __restrict__ WU_b) {
    int idx = blockIdx.x * blockDim.x + threadIdx.x;
    const int total = 32 * 9 * 128 * 64;   // (nblk,kt,row,pair)
    for (int i = idx; i < total; i += gridDim.x * blockDim.x) {
        int pc  = i & 63;
        int row = (i >> 6) & 127;
        int t2  = i >> 13;
        int kt  = t2 % 9;
        int nblk = t2 / 9;
        int np = nblk * 128 + row;
        size_t n = (size_t)((np & 3) * HIDDEN + (np >> 2));
        int k2 = kt * 128 + pc * 2;
        __half lo = __float2half(WU_w[n * KIN + k2 + 2]);
        __half hi = __float2half(WU_w[n * KIN + k2 + 3]);
        uint32_t v = (uint32_t)__half_as_ushort(lo) | ((uint32_t)__half_as_ushort(hi) << 16);
        char* base = (char*)g_Wblob + ((size_t)(nblk * 9 + kt) << 15);
        *(uint32_t*)(base + swz_off(row, pc * 2)) = v;
    }
    if (idx < NG) {
        int n = (idx & 3) * HIDDEN + (idx >> 2);
        g_bint[idx] = WU_b[n];
        g_Wx[idx * 2 + 0] = WU_w[(size_t)n * KIN + 0];
        g_Wx[idx * 2 + 1] = WU_w[(size_t)n * KIN + 1];
    }
}

__global__ void init_state(const float* __restrict__ z0,
                           const float* __restrict__ c_z0,
                           const float* __restrict__ rnn_input) {
    int b = blockIdx.x, tid = threadIdx.x;
    int grp = b >> 6, row = b & 63;
    for (int pc = tid; pc < 576; pc += 256) {
        int k2 = pc * 2;
        float v0 = (k2 < 128)     ? rnn_input[(size_t)b * SEQ * INPUT + k2]
                                  : z0[b * ZS + 2 + (k2 - 128)];
        float v1 = (k2 + 1 < 128) ? rnn_input[(size_t)b * SEQ * INPUT + k2 + 1]
                                  : z0[b * ZS + 2 + (k2 + 1 - 128)];
        __half lo = __float2half(v0), hi = __float2half(v1);
        uint32_t v = (uint32_t)__half_as_ushort(lo) | ((uint32_t)__half_as_ushort(hi) << 16);
        int kt = k2 >> 7, kc = k2 & 127;
        char* base = (char*)g_Ablob + ((size_t)((0 * 4 + grp) * 9 + kt) << 14);
        *(uint32_t*)(base + swz_off(row, kc)) = v;
    }
    if (tid < 2) {
        float xv = z0[b * ZS + tid];
        g_x[b * 2 + tid] = xv;
        g_x[BATCH * 2 + b * 2 + tid] = xv;
    }
    for (int j = tid; j < HIDDEN; j += 256)
        g_c[b * HIDDEN + j] = c_z0[b * ZS + 2 + j];
}

// ---------------------------------------------------------------------------
// Per-step kernel: 128 CTAs = 4 grp(64 rows) x 32 nblk(128 gate cols),
// 1024 threads / 32 warps, warp grid 4x8 (tile 16x16). BK=128 (9 iters),
// 3-stage cp.async.bulk ring. Coalesced smem-staged epilogue.
// ---------------------------------------------------------------------------
__global__ void __launch_bounds__(1024) step_kernel(
    const float* __restrict__ rnn_input, const float* __restrict__ tau,
    const float* __restrict__ alpha_w,   const float* __restrict__ alpha_b,
    const float* __restrict__ Whx_w,     const float* __restrict__ Whx_b,
    float* __restrict__ out, int t)
{
    extern __shared__ __align__(16) unsigned char dynsm[];   // 3*STG_B
    __shared__ __align__(8) unsigned long long mbar[3];
    __shared__ float2 s_wx[128];
    __shared__ float2 s_x[64];
    __shared__ float  s_aw0[32], s_aw1[32], s_wv0[32], s_wv1[32];

    const int tid  = threadIdx.x;
    const int grp  = blockIdx.x >> 5;
    const int nblk = blockIdx.x & 31;
    const int m0   = grp * 64;
    const int n0   = nblk * 128;
    const int lane = tid & 31, wid = tid >> 5;
    const int warp_m = wid >> 3, warp_n = wid & 7;   // 4x8 warp grid
    const int r = lane >> 2, q = lane & 3;
    const int p  = t & 1;
    const int pn = p ^ 1;

    const uint32_t smb = (uint32_t)__cvta_generic_to_shared(dynsm);
    uint32_t mb[3];
    #pragma unroll
    for (int i = 0; i < 3; i++) mb[i] = (uint32_t)__cvta_generic_to_shared(&mbar[i]);

    if (tid == 0) {
        #pragma unroll
        for (int i = 0; i < 3; i++)
            asm volatile("mbarrier.init.shared.b64 [%0], 1;" :: "r"(mb[i]) : "memory");
    }
    if (tid < 128)
        s_wx[tid] = make_float2(g_Wx[(n0 + tid) * 2], g_Wx[(n0 + tid) * 2 + 1]);
    if (tid >= 128 && tid < 160) {
        int i = tid - 128;
        int jg = nblk * 32 + i;
        s_aw0[i] = alpha_w[jg];
        s_aw1[i] = alpha_w[HIDDEN + jg];
        s_wv0[i] = Whx_w[jg];
        s_wv1[i] = Whx_w[HIDDEN + jg];
    }
    __syncthreads();

    const char* srcA = (const char*)g_Ablob + ((size_t)(p * 4 + grp) * 9 << 14);
    const char* srcW = (const char*)g_Wblob + ((size_t)nblk * 9 << 15);

    #define ISSUE(kt_) do {                                                      \
        const int _kt = (kt_);                                                   \
        const int _s = _kt % 3;                                                  \
        const uint32_t _d = smb + (uint32_t)_s * STG_B;                          \
        asm volatile("mbarrier.arrive.expect_tx.shared.b64 _, [%0], %1;"         \
                     :: "r"(mb[_s]), "r"(49152u) : "memory");                    \
        asm volatile("cp.async.bulk.shared::cluster.global.mbarrier::complete_tx::bytes " \
                     "[%0], [%1], %2, [%3];"                                     \
                     :: "r"(_d), "l"(srcA + ((size_t)_kt << 14)), "r"(16384u),   \
                        "r"(mb[_s]) : "memory");                                 \
        asm volatile("cp.async.bulk.shared::cluster.global.mbarrier::complete_tx::bytes " \
                     "[%0], [%1], %2, [%3];"                                     \
                     :: "r"(_d + OFF_W), "l"(srcW + ((size_t)_kt << 15)),        \
                        "r"(32768u), "r"(mb[_s]) : "memory");                    \
    } while (0)

    if (tid == 0) { ISSUE(0); ISSUE(1); ISSUE(2); }

    // ---------------- phase A (hoisted): x_t from prev-step parts ----------
    {
        const float4* pp = g_part + (size_t)(pn * 4 + grp) * 64 * 32;
        #pragma unroll 1
        for (int rr = 0; rr < 2; rr++) {
            const int row = wid * 2 + rr;
            const int b = m0 + row;
            float x0, x1;
            if (t == 0) {
                if (lane == 0) {
                    x0 = g_x[BATCH * 2 + b * 2];
                    x1 = g_x[BATCH * 2 + b * 2 + 1];
                }
            } else {
                float4 v = __ldcg(pp + row * 32 + lane);
                #pragma unroll
                for (int off = 16; off > 0; off >>= 1) {
                    v.x += __shfl_xor_sync(0xffffffffu, v.x, off);
                    v.y += __shfl_xor_sync(0xffffffffu, v.y, off);
                    v.z += __shfl_xor_sync(0xffffffffu, v.z, off);
                    v.w += __shfl_xor_sync(0xffffffffu, v.w, off);
                }
                if (lane == 0) {
                    float al0 = sigf(v.x + alpha_b[0]);
                    float al1 = sigf(v.y + alpha_b[1]);
                    float hx0 = v.z + Whx_b[0];
                    float hx1 = v.w + Whx_b[1];
                    float xp0 = g_x[pn * BATCH * 2 + b * 2];
                    float xp1 = g_x[pn * BATCH * 2 + b * 2 + 1];
                    float tv = tau[(size_t)b * SEQ + (t - 1)];
                    float xm0 = (1.f + tv * MHU) * xp0 - (tv * MHU) * xp1;
                    float xm1 = tv * (1.f / MHU) * xp0 + xp1;
                    x0 = al0 * xm0 + (1.f - al0) * hx0;
                    x1 = al1 * xm1 + (1.f - al1) * hx1;
                }
            }
            if (lane == 0) {
                s_x[row] = make_float2(x0, x1);
                if (nblk == 0) {
                    g_x[p * BATCH * 2 + b * 2]     = x0;
                    g_x[p * BATCH * 2 + b * 2 + 1] = x1;
                    if (t > 0) {
                        float* prow = out + ((size_t)b * SEQ + (t - 1)) * ZS;
                        prow[0] = x0;
                        prow[1] = x1;
                    }
                }
            }
        }
    }

    // ---- per-lane ldmatrix swizzled offsets ----
    const int aRow = warp_m * 16 + (lane & 7) + ((lane >> 3) & 1) * 8;
    const int bRow = warp_n * 16 + (lane & 7) + ((lane >> 4) & 1) * 8;
    const int aXor = (aRow >> 1) & 3;
    const int wXor = (bRow >> 1) & 3;
    const uint32_t aBase0 = (uint32_t)(aRow * 256 + ((((lane >> 4) & 1) ^ (aRow & 1)) << 4));
    const uint32_t bBase0 = (uint32_t)(OFF_W + bRow * 256 + ((((lane >> 3) & 1) ^ (bRow & 1)) << 4));

    float acc[2][4] = {};

    #pragma unroll 1
    for (int it = 0; it < NIT; it++) {
        const int s = it % 3;
        mwait(mb[s], (uint32_t)((it / 3) & 1));

        const uint32_t S = smb + (uint32_t)s * STG_B;
        const uint32_t aB = S + aBase0;
        const uint32_t bB = S + bBase0;

        #pragma unroll
        for (int c = 0; c < 8; c++) {
            uint32_t ah[4], bw[4];
            ldsm4(ah, aB + (uint32_t)((c ^ aXor) << 5));
            ldsm4(bw, bB + (uint32_t)((c ^ wXor) << 5));
            mma16816(acc[0], ah, bw + 0);
            mma16816(acc[1], ah, bw + 2);
        }
        __syncthreads();
        if (it + 3 < NIT && tid == 0) ISSUE(it + 3);
    }

    // ---------------- epilogue: dump acc to smem gate buffer ----------------
    float* SG = (float*)dynsm;                       // [64][SGS]
    __half* hbuf = (__half*)(dynsm + 2 * STG_B);     // [64][32]
    {
        const int gr = warp_m * 16 + r;
        #pragma unroll
        for (int j = 0; j < 2; j++) {
            const int col = warp_n * 16 + j * 8 + q * 2;
            SG[gr * SGS + col]           = acc[j][0];
            SG[gr * SGS + col + 1]       = acc[j][1];
            SG[(gr + 8) * SGS + col]     = acc[j][2];
            SG[(gr + 8) * SGS + col + 1] = acc[j][3];
        }
    }
    __syncthreads();

    // ---------------- coalesced pointwise pass: 2 units per thread ----------
    char* dstA = (char*)g_Ablob + ((size_t)(pn * 4 + grp) * 9 << 14);
    {
        const int unit0 = tid * 2;
        const int row = unit0 >> 5;       // 0..63
        const int jl0 = unit0 & 31;       // 0,2,..,30
        const int b = m0 + row;
        const float2 xv = s_x[row];
        float d0 = 0.f, d1 = 0.f, d2 = 0.f, d3 = 0.f;
        float* crow = g_c + (size_t)b * HIDDEN + nblk * 32;
        float* orow = out + ((size_t)b * SEQ + t) * ZS + 2 + nblk * 32;
        #pragma unroll
        for (int e = 0; e < 2; e++) {
            const int jl = jl0 + e;
            const int jg = nblk * 32 + jl;
            float4 gv = *(const float4*)(SG + row * SGS + 4 * jl);
            float4 bv = *(const float4*)(g_bint + 4 * jg);
            float2 w0 = s_wx[4 * jl + 0];
            float2 w1 = s_wx[4 * jl + 1];
            float2 w2 = s_wx[4 * jl + 2];
            float2 w3 = s_wx[4 * jl + 3];
            float gi = gv.x + bv.x + xv.x * w0.x + xv.y * w0.y;
            float gf = gv.y + bv.y + xv.x * w1.x + xv.y * w1.y;
            float gg = gv.z + bv.z + xv.x * w2.x + xv.y * w2.y;
            float go = gv.w + bv.w + xv.x * w3.x + xv.y * w3.y;
            float co = crow[jl];
            float cn = sigf(gf) * co + sigf(gi) * tanhfast(gg);
            float h  = sigf(go) * tanhfast(cn);
            crow[jl] = cn;
            orow[jl] = h;
            hbuf[row * 32 + jl] = __float2half(h);
            d0 += h * s_aw0[jl];
            d1 += h * s_aw1[jl];
            d2 += h * s_wv0[jl];
            d3 += h * s_wv1[jl];
        }
        #pragma unroll
        for (int off = 1; off < 16; off <<= 1) {
            d0 += __shfl_xor_sync(0xffffffffu, d0, off);
            d1 += __shfl_xor_sync(0xffffffffu, d1, off);
            d2 += __shfl_xor_sync(0xffffffffu, d2, off);
            d3 += __shfl_xor_sync(0xffffffffu, d3, off);
        }
        if ((tid & 15) == 0)
            g_part[((size_t)(p * 4 + grp) * 64 + row) * 32 + nblk] =
                make_float4(d0, d1, d2, d3);
    }
    __syncthreads();

    // ---- h writeback: 16B swizzled chunks (8 halves each) ----
    if (tid < 256) {
        int row = tid >> 2;          // 0..63
        int cg  = tid & 3;           // 4 chunks of 8 halves
        uint4 v = *(const uint4*)(hbuf + row * 32 + cg * 8);
        int k = 128 + nblk * 32 + cg * 8;
        int kt = k >> 7, kc = k & 127;
        *(uint4*)(dstA + ((size_t)kt << 14) + swz_off(row, kc)) = v;
    }
    // ---- u_{t+1} staging: 2 rows per CTA, 16B chunks ----
    else if (t + 1 < SEQ && tid >= 256 && tid < 288) {
        int tid2 = tid - 256;        // 0..31
        int row = 2 * nblk + (tid2 >> 4);
        int cg  = tid2 & 15;         // chunk of 8 cols
        int b = m0 + row;
        const float4* up = (const float4*)(rnn_input + ((size_t)b * SEQ + (t + 1)) * INPUT + cg * 8);
        float4 u0 = up[0], u1 = up[1];
        uint4 v;
        v.x = (uint32_t)__half_as_ushort(__float2half(u0.x)) |
              ((uint32_t)__half_as_ushort(__float2half(u0.y)) << 16);
        v.y = (uint32_t)__half_as_ushort(__float2half(u0.z)) |
              ((uint32_t)__half_as_ushort(__float2half(u0.w)) << 16);
        v.z = (uint32_t)__half_as_ushort(__float2half(u1.x)) |
              ((uint32_t)__half_as_ushort(__float2half(u1.y)) << 16);
        v.w = (uint32_t)__half_as_ushort(__float2half(u1.z)) |
              ((uint32_t)__half_as_ushort(__float2half(u1.w)) << 16);
        *(uint4*)(dstA + swz_off(row, cg * 8)) = v;    // kt = 0
    }
}

// ---------------------------------------------------------------------------
__global__ void finalize(const float* __restrict__ tau,
                         const float* __restrict__ alpha_b, const float* __restrict__ Whx_b,
                         const float* __restrict__ c_z0, float* __restrict__ out) {
    int b = blockIdx.x, tid = threadIdx.x;
    __shared__ float2 s_xf;
    if (tid < 32) {
        const float4* pp = g_part + (size_t)(1 * 4 + (b >> 6)) * 64 * 32 + (size_t)(b & 63) * 32;
        float4 v = __ldcg(pp + tid);
        #pragma unroll
        for (int off = 16; off > 0; off >>= 1) {
            v.x += __shfl_xor_sync(0xffffffffu, v.x, off);
            v.y += __shfl_xor_sync(0xffffffffu, v.y, off);
            v.z += __shfl_xor_sync(0xffffffffu, v.z, off);
            v.w += __shfl_xor_sync(0xffffffffu, v.w, off);
        }
        if (tid == 0) {
            float al0 = sigf(v.x + alpha_b[0]);
            float al1 = sigf(v.y + alpha_b[1]);
            float hx0 = v.z + Whx_b[0];
            float hx1 = v.w + Whx_b[1];
            float xp0 = g_x[BATCH * 2 + b * 2];       // parity 1 = step 255
            float xp1 = g_x[BATCH * 2 + b * 2 + 1];
            float tv = tau[(size_t)b * SEQ + (SEQ - 1)];
            float xm0 = (1.f + tv * MHU) * xp0 - (tv * MHU) * xp1;
            float xm1 = tv * (1.f / MHU) * xp0 + xp1;
            float x0 = al0 * xm0 + (1.f - al0) * hx0;
            float x1 = al1 * xm1 + (1.f - al1) * hx1;
            float* prow = out + ((size_t)b * SEQ + (SEQ - 1)) * ZS;
            prow[0] = x0; prow[1] = x1;
            s_xf = make_float2(x0, x1);
        }
    }
    __syncthreads();
    size_t base = (size_t)BATCH * SEQ * ZS;
    float* zf  = out + base + (size_t)b * ZS;
    float* czf = out + base + (size_t)BATCH * ZS + (size_t)b * ZS;
    const float* last = out + ((size_t)b * SEQ + (SEQ - 1)) * ZS;
    for (int k = tid; k < ZS; k += 256) {
        zf[k]  = (k == 0) ? s_xf.x : (k == 1) ? s_xf.y : last[k];
        czf[k] = (k < 2) ? c_z0[b * ZS + k] : g_c[(size_t)b * HIDDEN + (k - 2)];
    }
}

// ---------------------------------------------------------------------------
extern "C" void kernel_launch(void* const* d_in, const int* in_sizes, int n_in,
                              void* d_out, int out_size) {
    const float* rnn_input = (const float*)d_in[0];
    const float* tau       = (const float*)d_in[1];
    const float* z0        = (const float*)d_in[2];
    const float* c_z0      = (const float*)d_in[3];
    const float* WU_w      = (const float*)d_in[4];
    const float* WU_b      = (const float*)d_in[5];
    const float* alpha_w   = (const float*)d_in[6];
    const float* alpha_b   = (const float*)d_in[7];
    const float* Whx_w     = (const float*)d_in[8];
    const float* Whx_b     = (const float*)d_in[9];
    float* out = (float*)d_out;

    static bool attr_set = false;
    if (!attr_set) {
        cudaFuncSetAttribute(step_kernel, cudaFuncAttributeMaxDynamicSharedMemorySize,
                             3 * STG_B);
        attr_set = true;
    }

    repack<<<4096, 256>>>(WU_w, WU_b);
    init_state<<<BATCH, 256>>>(z0, c_z0, rnn_input);
    for (int t = 0; t < SEQ; t++) {
        step_kernel<<<128, 1024, 3 * STG_B>>>(rnn_input, tau, alpha_w, alpha_b,
                                              Whx_w, Whx_b, out, t);
    }
    finalize<<<BATCH, 256>>>(tau, alpha_b, Whx_b, c_z0, out);
}